// round 1
// baseline (speedup 1.0000x reference)
#include <cuda_runtime.h>
#include <cuda_pipeline.h>
#include <mma.h>
#include <math.h>
#include <stdint.h>

using namespace nvcuda;

#define NTOK 8192
#define HID 2048
#define NHEAD 16
#define DHEAD 128
#define FFN 8192

// ---------------- scratch (no allocation allowed; __device__ globals) ------
__device__ float g_t0 [(size_t)NTOK * HID];
__device__ float g_t1 [(size_t)NTOK * HID];
__device__ float g_P  [(size_t)NTOK * HID];
__device__ float g_D  [(size_t)NTOK * HID];
__device__ float g_R  [(size_t)NTOK * HID];
__device__ float g_Q  [(size_t)NTOK * HID];
__device__ float g_K  [(size_t)NTOK * HID];
__device__ float g_V  [(size_t)NTOK * HID];
__device__ float g_att[(size_t)NTOK * HID];
__device__ float g_X1 [(size_t)NTOK * HID];
__device__ float g_F1 [(size_t)NTOK * FFN];

// ---------------- GEMM: C = epi(A @ B + bias), tf32 tensor cores ----------
// A: [M,K] row-major fp32, B: [K,N] row-major fp32, C: [M,N] fp32
// EPI: 0 = bias only, 1 = relu, 2 = leaky(0.01), 3 = extra - x, 4 = x + extra
#define BM 128
#define BN 128
#define BK 16

template<int EPI>
__global__ void __launch_bounds__(256) gemm_tf32_kernel(
    const float* __restrict__ A, const float* __restrict__ B,
    const float* __restrict__ bias, const float* __restrict__ extra,
    float* __restrict__ C, int M, int Nn, int Kk)
{
    __shared__ __align__(16) float sA[2][BM * BK];
    __shared__ __align__(16) float sB[2][BK * BN];
    __shared__ __align__(16) float sOut[8][256];

    const int t    = threadIdx.x;
    const int warp = t >> 5;
    const int lane = t & 31;
    const int bm   = blockIdx.y;
    const int bn   = blockIdx.x;
    const int wm   = warp & 3;   // 4 warps along M
    const int wn   = warp >> 2;  // 2 warps along N

    const float* Ab = A + (size_t)bm * BM * Kk;
    const float* Bb = B + (size_t)bn * BN;

    wmma::fragment<wmma::accumulator, 16, 16, 8, float> acc[2][4];
    #pragma unroll
    for (int i = 0; i < 2; i++)
        #pragma unroll
        for (int j = 0; j < 4; j++)
            wmma::fill_fragment(acc[i][j], 0.0f);

    const int KT = Kk / BK;

    auto load_tiles = [&](int stage, int kt) {
        // A tile: 128 x 16 = 512 float4, 2 per thread
        #pragma unroll
        for (int i = t; i < 512; i += 256) {
            int r = i >> 2, c4 = i & 3;
            __pipeline_memcpy_async(&sA[stage][r * BK + c4 * 4],
                                    Ab + (size_t)r * Kk + kt * BK + c4 * 4, 16);
        }
        // B tile: 16 x 128 = 512 float4, 2 per thread
        #pragma unroll
        for (int i = t; i < 512; i += 256) {
            int r = i >> 5, c4 = i & 31;
            __pipeline_memcpy_async(&sB[stage][r * BN + c4 * 4],
                                    Bb + (size_t)(kt * BK + r) * Nn + c4 * 4, 16);
        }
    };

    load_tiles(0, 0);
    __pipeline_commit();

    for (int kt = 0; kt < KT; ++kt) {
        if (kt + 1 < KT) {
            load_tiles((kt + 1) & 1, kt + 1);
            __pipeline_commit();
            __pipeline_wait_prior(1);
        } else {
            __pipeline_wait_prior(0);
        }
        __syncthreads();

        const int cur = kt & 1;
        #pragma unroll
        for (int ks = 0; ks < 2; ++ks) {
            wmma::fragment<wmma::matrix_a, 16, 16, 8, wmma::precision::tf32, wmma::row_major> afr[2];
            wmma::fragment<wmma::matrix_b, 16, 16, 8, wmma::precision::tf32, wmma::row_major> bfr[4];
            #pragma unroll
            for (int fm = 0; fm < 2; ++fm) {
                wmma::load_matrix_sync(afr[fm], &sA[cur][(wm * 32 + fm * 16) * BK + ks * 8], BK);
                #pragma unroll
                for (int e = 0; e < afr[fm].num_elements; e++)
                    afr[fm].x[e] = wmma::__float_to_tf32(afr[fm].x[e]);
            }
            #pragma unroll
            for (int fn = 0; fn < 4; ++fn) {
                wmma::load_matrix_sync(bfr[fn], &sB[cur][(ks * 8) * BN + wn * 64 + fn * 16], BN);
                #pragma unroll
                for (int e = 0; e < bfr[fn].num_elements; e++)
                    bfr[fn].x[e] = wmma::__float_to_tf32(bfr[fn].x[e]);
            }
            #pragma unroll
            for (int fm = 0; fm < 2; ++fm)
                #pragma unroll
                for (int fn = 0; fn < 4; ++fn)
                    wmma::mma_sync(acc[fm][fn], afr[fm], bfr[fn], acc[fm][fn]);
        }
        __syncthreads();
    }

    // epilogue through per-warp smem scratch (portable acc layout)
    const size_t row0 = (size_t)bm * BM;
    const int    col0 = bn * BN;
    #pragma unroll
    for (int fm = 0; fm < 2; ++fm) {
        #pragma unroll
        for (int fn = 0; fn < 4; ++fn) {
            wmma::store_matrix_sync(&sOut[warp][0], acc[fm][fn], 16, wmma::mem_row_major);
            __syncwarp();
            const int r0 = wm * 32 + fm * 16;
            const int c0 = wn * 64 + fn * 16;
            #pragma unroll
            for (int e = lane; e < 256; e += 32) {
                int r = e >> 4, c = e & 15;
                size_t gr = row0 + r0 + r;
                int    gc = col0 + c0 + c;
                float  v  = sOut[warp][e] + bias[gc];
                if (EPI == 1) v = fmaxf(v, 0.0f);
                else if (EPI == 2) v = (v >= 0.0f) ? v : 0.01f * v;
                else if (EPI == 3) v = extra[gr * (size_t)Nn + gc] - v;
                else if (EPI == 4) v = v + extra[gr * (size_t)Nn + gc];
                C[gr * (size_t)Nn + gc] = v;
            }
            __syncwarp();
        }
    }
}

// ---------------- per-token head-vs-head attention (exact fp32) ------------
__global__ void __launch_bounds__(128) attn_kernel(
    const float* __restrict__ Q, const float* __restrict__ K,
    const float* __restrict__ V, const float* __restrict__ R,
    float* __restrict__ out)
{
    __shared__ __align__(16) float sQ[NHEAD][DHEAD];
    __shared__ __align__(16) float sK[NHEAD][DHEAD];
    __shared__ __align__(16) float sV[NHEAD][DHEAD];
    __shared__ __align__(16) float sR[NHEAD][DHEAD];

    const int n = blockIdx.x;
    const int t = threadIdx.x;
    const size_t base = (size_t)n * HID;

    const float4* q4 = (const float4*)(Q + base);
    const float4* k4 = (const float4*)(K + base);
    const float4* v4 = (const float4*)(V + base);
    const float4* r4 = (const float4*)(R + base);
    #pragma unroll
    for (int i = t; i < HID / 4; i += 128) {
        ((float4*)sQ)[i] = q4[i];
        ((float4*)sK)[i] = k4[i];
        ((float4*)sV)[i] = v4[i];
        ((float4*)sR)[i] = r4[i];
    }
    __syncthreads();

    const int warp = t >> 5, lane = t & 31;
    const float scale = 0.08838834764831845f;  // 1/sqrt(128)

    #pragma unroll
    for (int hh = 0; hh < 4; ++hh) {
        const int h = warp * 4 + hh;
        const float q0 = sQ[h][lane], q1 = sQ[h][lane + 32];
        const float q2 = sQ[h][lane + 64], q3 = sQ[h][lane + 96];

        float sc[NHEAD];
        #pragma unroll
        for (int g = 0; g < NHEAD; ++g) {
            float s1 = q0 * sK[g][lane] + q1 * sK[g][lane + 32]
                     + q2 * sK[g][lane + 64] + q3 * sK[g][lane + 96];
            float s2 = q0 * sR[g][lane] + q1 * sR[g][lane + 32]
                     + q2 * sR[g][lane + 64] + q3 * sR[g][lane + 96];
            float v = s1 * scale - s2;
            #pragma unroll
            for (int o = 16; o > 0; o >>= 1) v += __shfl_xor_sync(0xffffffffu, v, o);
            sc[g] = v;
        }
        float m = sc[0];
        #pragma unroll
        for (int g = 1; g < NHEAD; ++g) m = fmaxf(m, sc[g]);
        float den = 0.0f;
        #pragma unroll
        for (int g = 0; g < NHEAD; ++g) { sc[g] = expf(sc[g] - m); den += sc[g]; }
        const float inv = 1.0f / den;

        float o0 = 0, o1 = 0, o2 = 0, o3 = 0;
        #pragma unroll
        for (int g = 0; g < NHEAD; ++g) {
            float p = sc[g] * inv;
            o0 += p * sV[g][lane];
            o1 += p * sV[g][lane + 32];
            o2 += p * sV[g][lane + 64];
            o3 += p * sV[g][lane + 96];
        }
        float* op = out + base + (size_t)h * DHEAD;
        op[lane] = o0; op[lane + 32] = o1; op[lane + 64] = o2; op[lane + 96] = o3;
    }
}

// ---------------- layernorm: out = LN(x)*gamma + beta ----------------------
__global__ void __launch_bounds__(256) ln_kernel(
    const float* __restrict__ x, const float* __restrict__ gamma,
    const float* __restrict__ beta, float* __restrict__ out)
{
    __shared__ float sh[8];
    const int row = blockIdx.x, t = threadIdx.x;
    const int lane = t & 31, w = t >> 5;

    const float4* xr = (const float4*)(x + (size_t)row * HID);
    float4 a = xr[t];
    float4 b = xr[t + 256];

    float s = a.x + a.y + a.z + a.w + b.x + b.y + b.z + b.w;
    #pragma unroll
    for (int o = 16; o > 0; o >>= 1) s += __shfl_xor_sync(0xffffffffu, s, o);
    if (lane == 0) sh[w] = s;
    __syncthreads();
    float tot = 0;
    #pragma unroll
    for (int i = 0; i < 8; i++) tot += sh[i];
    const float mean = tot * (1.0f / HID);

    float d, sq = 0;
    d = a.x - mean; sq += d * d;  d = a.y - mean; sq += d * d;
    d = a.z - mean; sq += d * d;  d = a.w - mean; sq += d * d;
    d = b.x - mean; sq += d * d;  d = b.y - mean; sq += d * d;
    d = b.z - mean; sq += d * d;  d = b.w - mean; sq += d * d;
    __syncthreads();  // protect sh reuse
    #pragma unroll
    for (int o = 16; o > 0; o >>= 1) sq += __shfl_xor_sync(0xffffffffu, sq, o);
    if (lane == 0) sh[w] = sq;
    __syncthreads();
    tot = 0;
    #pragma unroll
    for (int i = 0; i < 8; i++) tot += sh[i];
    const float rstd = rsqrtf(tot * (1.0f / HID) + 1e-5f);

    const float4* g4 = (const float4*)gamma;
    const float4* e4 = (const float4*)beta;
    float4 g0 = g4[t], gA = g4[t + 256], e0 = e4[t], eA = e4[t + 256];
    float4* o4 = (float4*)(out + (size_t)row * HID);
    o4[t] = make_float4((a.x - mean) * rstd * g0.x + e0.x,
                        (a.y - mean) * rstd * g0.y + e0.y,
                        (a.z - mean) * rstd * g0.z + e0.z,
                        (a.w - mean) * rstd * g0.w + e0.w);
    o4[t + 256] = make_float4((b.x - mean) * rstd * gA.x + eA.x,
                              (b.y - mean) * rstd * gA.y + eA.y,
                              (b.z - mean) * rstd * gA.z + eA.z,
                              (b.w - mean) * rstd * gA.w + eA.w);
}

// ---------------- host orchestration ---------------------------------------
static void run_gemm(int epi, const float* A, const float* B, const float* bias,
                     const float* extra, float* C, int M, int Nn, int Kk)
{
    dim3 grid(Nn / 128, M / 128), block(256);
    switch (epi) {
        case 0: gemm_tf32_kernel<0><<<grid, block>>>(A, B, bias, extra, C, M, Nn, Kk); break;
        case 1: gemm_tf32_kernel<1><<<grid, block>>>(A, B, bias, extra, C, M, Nn, Kk); break;
        case 2: gemm_tf32_kernel<2><<<grid, block>>>(A, B, bias, extra, C, M, Nn, Kk); break;
        case 3: gemm_tf32_kernel<3><<<grid, block>>>(A, B, bias, extra, C, M, Nn, Kk); break;
        case 4: gemm_tf32_kernel<4><<<grid, block>>>(A, B, bias, extra, C, M, Nn, Kk); break;
    }
}

extern "C" void kernel_launch(void* const* d_in, const int* in_sizes, int n_in,
                              void* d_out, int out_size)
{
    const float* E   = (const float*)d_in[0];
    const float* Obs = (const float*)d_in[1];
    const float* pw1 = (const float*)d_in[2];
    const float* pb1 = (const float*)d_in[3];
    const float* pw2 = (const float*)d_in[4];
    const float* pb2 = (const float*)d_in[5];
    const float* ow1 = (const float*)d_in[6];
    const float* ob1 = (const float*)d_in[7];
    const float* ow2 = (const float*)d_in[8];
    const float* ob2 = (const float*)d_in[9];
    const float* rw1 = (const float*)d_in[10];
    const float* rb1 = (const float*)d_in[11];
    const float* rw2 = (const float*)d_in[12];
    const float* rb2 = (const float*)d_in[13];
    const float* wq  = (const float*)d_in[14];
    const float* bq  = (const float*)d_in[15];
    const float* wk  = (const float*)d_in[16];
    const float* bk  = (const float*)d_in[17];
    const float* wv  = (const float*)d_in[18];
    const float* bv  = (const float*)d_in[19];
    const float* wo  = (const float*)d_in[20];
    const float* bo  = (const float*)d_in[21];
    const float* fw1 = (const float*)d_in[22];
    const float* fb1 = (const float*)d_in[23];
    const float* fw2 = (const float*)d_in[24];
    const float* fb2 = (const float*)d_in[25];
    const float* g1  = (const float*)d_in[26];
    const float* be1 = (const float*)d_in[27];
    const float* g2  = (const float*)d_in[28];
    const float* be2 = (const float*)d_in[29];
    float* out = (float*)d_out;

    float *t0, *t1, *P, *Dd, *R, *Q, *K, *V, *att, *X1, *F1;
    cudaGetSymbolAddress((void**)&t0,  g_t0);
    cudaGetSymbolAddress((void**)&t1,  g_t1);
    cudaGetSymbolAddress((void**)&P,   g_P);
    cudaGetSymbolAddress((void**)&Dd,  g_D);
    cudaGetSymbolAddress((void**)&R,   g_R);
    cudaGetSymbolAddress((void**)&Q,   g_Q);
    cudaGetSymbolAddress((void**)&K,   g_K);
    cudaGetSymbolAddress((void**)&V,   g_V);
    cudaGetSymbolAddress((void**)&att, g_att);
    cudaGetSymbolAddress((void**)&X1,  g_X1);
    cudaGetSymbolAddress((void**)&F1,  g_F1);

    // predictor MLP: P = relu(E@pw1+pb1) @ pw2 + pb2
    run_gemm(1, E,   pw1, pb1, nullptr, t0, NTOK, HID, HID);
    run_gemm(0, t0,  pw2, pb2, nullptr, P,  NTOK, HID, HID);
    // observation mapper, fused into D = P - (relu(Obs@ow1+ob1)@ow2+ob2)
    run_gemm(1, Obs, ow1, ob1, nullptr, t1, NTOK, HID, HID);
    run_gemm(3, t1,  ow2, ob2, P,       Dd, NTOK, HID, HID);
    // residual MLP: R = relu(D@rw1+rb1) @ rw2 + rb2
    run_gemm(1, Dd,  rw1, rb1, nullptr, t0, NTOK, HID, HID);
    run_gemm(0, t0,  rw2, rb2, nullptr, R,  NTOK, HID, HID);
    // Q/K/V projections
    run_gemm(0, E, wq, bq, nullptr, Q, NTOK, HID, HID);
    run_gemm(0, E, wk, bk, nullptr, K, NTOK, HID, HID);
    run_gemm(0, E, wv, bv, nullptr, V, NTOK, HID, HID);
    // per-token residual-adjusted attention
    attn_kernel<<<NTOK, 128>>>(Q, K, V, R, att);
    // output projection, fused residual add: t0 = E + att@wo + bo
    run_gemm(4, att, wo, bo, E, t0, NTOK, HID, HID);
    // X1 = LN(t0)
    ln_kernel<<<NTOK, 256>>>(t0, g1, be1, X1);
    // FFN: F1 = leaky(X1@fw1+fb1), t0 = X1 + F1@fw2 + fb2
    run_gemm(2, X1, fw1, fb1, nullptr, F1, NTOK, FFN, HID);
    run_gemm(4, F1, fw2, fb2, X1,      t0, NTOK, HID, FFN);
    // out = LN(t0)
    ln_kernel<<<NTOK, 256>>>(t0, g2, be2, out);
}

// round 2
// speedup vs baseline: 1.0006x; 1.0006x over previous
#include <cuda_runtime.h>
#include <cuda_pipeline.h>
#include <mma.h>
#include <math.h>
#include <stdint.h>

using namespace nvcuda;

#define NTOK 8192
#define HID 2048
#define NHEAD 16
#define DHEAD 128
#define FFN 8192

// ---------------- scratch (no allocation allowed; __device__ globals) ------
__device__ float g_t0 [(size_t)NTOK * HID];
__device__ float g_t1 [(size_t)NTOK * HID];
__device__ float g_P  [(size_t)NTOK * HID];
__device__ float g_D  [(size_t)NTOK * HID];
__device__ float g_R  [(size_t)NTOK * HID];
__device__ float g_Q  [(size_t)NTOK * HID];
__device__ float g_K  [(size_t)NTOK * HID];
__device__ float g_V  [(size_t)NTOK * HID];
__device__ float g_att[(size_t)NTOK * HID];
__device__ float g_X1 [(size_t)NTOK * HID];
__device__ float g_F1 [(size_t)NTOK * FFN];

// ---------------- GEMM: C = epi(A @ B + bias), tf32 tensor cores ----------
// A: [M,K] row-major fp32, B: [K,N] row-major fp32, C: [M,N] fp32
// EPI: 0 = bias only, 1 = relu, 2 = leaky(0.01), 3 = extra - x, 4 = x + extra
#define BM 128
#define BN 128
#define BK 16

template<int EPI>
__global__ void __launch_bounds__(256) gemm_tf32_kernel(
    const float* __restrict__ A, const float* __restrict__ B,
    const float* __restrict__ bias, const float* __restrict__ extra,
    float* __restrict__ C, int M, int Nn, int Kk)
{
    __shared__ __align__(16) float sA[2][BM * BK];
    __shared__ __align__(16) float sB[2][BK * BN];
    __shared__ __align__(16) float sOut[8][256];

    const int t    = threadIdx.x;
    const int warp = t >> 5;
    const int lane = t & 31;
    const int bm   = blockIdx.y;
    const int bn   = blockIdx.x;
    const int wm   = warp & 3;   // 4 warps along M
    const int wn   = warp >> 2;  // 2 warps along N

    const float* Ab = A + (size_t)bm * BM * Kk;
    const float* Bb = B + (size_t)bn * BN;

    wmma::fragment<wmma::accumulator, 16, 16, 8, float> acc[2][4];
    #pragma unroll
    for (int i = 0; i < 2; i++)
        #pragma unroll
        for (int j = 0; j < 4; j++)
            wmma::fill_fragment(acc[i][j], 0.0f);

    const int KT = Kk / BK;

    auto load_tiles = [&](int stage, int kt) {
        // A tile: 128 x 16 = 512 float4, 2 per thread
        #pragma unroll
        for (int i = t; i < 512; i += 256) {
            int r = i >> 2, c4 = i & 3;
            __pipeline_memcpy_async(&sA[stage][r * BK + c4 * 4],
                                    Ab + (size_t)r * Kk + kt * BK + c4 * 4, 16);
        }
        // B tile: 16 x 128 = 512 float4, 2 per thread
        #pragma unroll
        for (int i = t; i < 512; i += 256) {
            int r = i >> 5, c4 = i & 31;
            __pipeline_memcpy_async(&sB[stage][r * BN + c4 * 4],
                                    Bb + (size_t)(kt * BK + r) * Nn + c4 * 4, 16);
        }
    };

    load_tiles(0, 0);
    __pipeline_commit();

    for (int kt = 0; kt < KT; ++kt) {
        if (kt + 1 < KT) {
            load_tiles((kt + 1) & 1, kt + 1);
            __pipeline_commit();
            __pipeline_wait_prior(1);
        } else {
            __pipeline_wait_prior(0);
        }
        __syncthreads();

        const int cur = kt & 1;
        #pragma unroll
        for (int ks = 0; ks < 2; ++ks) {
            wmma::fragment<wmma::matrix_a, 16, 16, 8, wmma::precision::tf32, wmma::row_major> afr[2];
            wmma::fragment<wmma::matrix_b, 16, 16, 8, wmma::precision::tf32, wmma::row_major> bfr[4];
            #pragma unroll
            for (int fm = 0; fm < 2; ++fm) {
                wmma::load_matrix_sync(afr[fm], &sA[cur][(wm * 32 + fm * 16) * BK + ks * 8], BK);
                #pragma unroll
                for (int e = 0; e < afr[fm].num_elements; e++)
                    afr[fm].x[e] = wmma::__float_to_tf32(afr[fm].x[e]);
            }
            #pragma unroll
            for (int fn = 0; fn < 4; ++fn) {
                wmma::load_matrix_sync(bfr[fn], &sB[cur][(ks * 8) * BN + wn * 64 + fn * 16], BN);
                #pragma unroll
                for (int e = 0; e < bfr[fn].num_elements; e++)
                    bfr[fn].x[e] = wmma::__float_to_tf32(bfr[fn].x[e]);
            }
            #pragma unroll
            for (int fm = 0; fm < 2; ++fm)
                #pragma unroll
                for (int fn = 0; fn < 4; ++fn)
                    wmma::mma_sync(acc[fm][fn], afr[fm], bfr[fn], acc[fm][fn]);
        }
        __syncthreads();
    }

    // epilogue through per-warp smem scratch (portable acc layout)
    const size_t row0 = (size_t)bm * BM;
    const int    col0 = bn * BN;
    #pragma unroll
    for (int fm = 0; fm < 2; ++fm) {
        #pragma unroll
        for (int fn = 0; fn < 4; ++fn) {
            wmma::store_matrix_sync(&sOut[warp][0], acc[fm][fn], 16, wmma::mem_row_major);
            __syncwarp();
            const int r0 = wm * 32 + fm * 16;
            const int c0 = wn * 64 + fn * 16;
            #pragma unroll
            for (int e = lane; e < 256; e += 32) {
                int r = e >> 4, c = e & 15;
                size_t gr = row0 + r0 + r;
                int    gc = col0 + c0 + c;
                float  v  = sOut[warp][e] + bias[gc];
                if (EPI == 1) v = fmaxf(v, 0.0f);
                else if (EPI == 2) v = (v >= 0.0f) ? v : 0.01f * v;
                else if (EPI == 3) v = extra[gr * (size_t)Nn + gc] - v;
                else if (EPI == 4) v = v + extra[gr * (size_t)Nn + gc];
                C[gr * (size_t)Nn + gc] = v;
            }
            __syncwarp();
        }
    }
}

// ---------------- per-token head-vs-head attention (exact fp32) ------------
__global__ void __launch_bounds__(128) attn_kernel(
    const float* __restrict__ Q, const float* __restrict__ K,
    const float* __restrict__ V, const float* __restrict__ R,
    float* __restrict__ out)
{
    __shared__ __align__(16) float sQ[NHEAD][DHEAD];
    __shared__ __align__(16) float sK[NHEAD][DHEAD];
    __shared__ __align__(16) float sV[NHEAD][DHEAD];
    __shared__ __align__(16) float sR[NHEAD][DHEAD];

    const int n = blockIdx.x;
    const int t = threadIdx.x;
    const size_t base = (size_t)n * HID;

    const float4* q4 = (const float4*)(Q + base);
    const float4* k4 = (const float4*)(K + base);
    const float4* v4 = (const float4*)(V + base);
    const float4* r4 = (const float4*)(R + base);
    #pragma unroll
    for (int i = t; i < HID / 4; i += 128) {
        ((float4*)sQ)[i] = q4[i];
        ((float4*)sK)[i] = k4[i];
        ((float4*)sV)[i] = v4[i];
        ((float4*)sR)[i] = r4[i];
    }
    __syncthreads();

    const int warp = t >> 5, lane = t & 31;
    const float scale = 0.08838834764831845f;  // 1/sqrt(128)

    #pragma unroll
    for (int hh = 0; hh < 4; ++hh) {
        const int h = warp * 4 + hh;
        const float q0 = sQ[h][lane], q1 = sQ[h][lane + 32];
        const float q2 = sQ[h][lane + 64], q3 = sQ[h][lane + 96];

        float sc[NHEAD];
        #pragma unroll
        for (int g = 0; g < NHEAD; ++g) {
            float s1 = q0 * sK[g][lane] + q1 * sK[g][lane + 32]
                     + q2 * sK[g][lane + 64] + q3 * sK[g][lane + 96];
            float s2 = q0 * sR[g][lane] + q1 * sR[g][lane + 32]
                     + q2 * sR[g][lane + 64] + q3 * sR[g][lane + 96];
            float v = s1 * scale - s2;
            #pragma unroll
            for (int o = 16; o > 0; o >>= 1) v += __shfl_xor_sync(0xffffffffu, v, o);
            sc[g] = v;
        }
        float m = sc[0];
        #pragma unroll
        for (int g = 1; g < NHEAD; ++g) m = fmaxf(m, sc[g]);
        float den = 0.0f;
        #pragma unroll
        for (int g = 0; g < NHEAD; ++g) { sc[g] = expf(sc[g] - m); den += sc[g]; }
        const float inv = 1.0f / den;

        float o0 = 0, o1 = 0, o2 = 0, o3 = 0;
        #pragma unroll
        for (int g = 0; g < NHEAD; ++g) {
            float p = sc[g] * inv;
            o0 += p * sV[g][lane];
            o1 += p * sV[g][lane + 32];
            o2 += p * sV[g][lane + 64];
            o3 += p * sV[g][lane + 96];
        }
        float* op = out + base + (size_t)h * DHEAD;
        op[lane] = o0; op[lane + 32] = o1; op[lane + 64] = o2; op[lane + 96] = o3;
    }
}

// ---------------- layernorm: out = LN(x)*gamma + beta ----------------------
__global__ void __launch_bounds__(256) ln_kernel(
    const float* __restrict__ x, const float* __restrict__ gamma,
    const float* __restrict__ beta, float* __restrict__ out)
{
    __shared__ float sh[8];
    const int row = blockIdx.x, t = threadIdx.x;
    const int lane = t & 31, w = t >> 5;

    const float4* xr = (const float4*)(x + (size_t)row * HID);
    float4 a = xr[t];
    float4 b = xr[t + 256];

    float s = a.x + a.y + a.z + a.w + b.x + b.y + b.z + b.w;
    #pragma unroll
    for (int o = 16; o > 0; o >>= 1) s += __shfl_xor_sync(0xffffffffu, s, o);
    if (lane == 0) sh[w] = s;
    __syncthreads();
    float tot = 0;
    #pragma unroll
    for (int i = 0; i < 8; i++) tot += sh[i];
    const float mean = tot * (1.0f / HID);

    float d, sq = 0;
    d = a.x - mean; sq += d * d;  d = a.y - mean; sq += d * d;
    d = a.z - mean; sq += d * d;  d = a.w - mean; sq += d * d;
    d = b.x - mean; sq += d * d;  d = b.y - mean; sq += d * d;
    d = b.z - mean; sq += d * d;  d = b.w - mean; sq += d * d;
    __syncthreads();  // protect sh reuse
    #pragma unroll
    for (int o = 16; o > 0; o >>= 1) sq += __shfl_xor_sync(0xffffffffu, sq, o);
    if (lane == 0) sh[w] = sq;
    __syncthreads();
    tot = 0;
    #pragma unroll
    for (int i = 0; i < 8; i++) tot += sh[i];
    const float rstd = rsqrtf(tot * (1.0f / HID) + 1e-5f);

    const float4* g4 = (const float4*)gamma;
    const float4* e4 = (const float4*)beta;
    float4 g0 = g4[t], gA = g4[t + 256], e0 = e4[t], eA = e4[t + 256];
    float4* o4 = (float4*)(out + (size_t)row * HID);
    o4[t] = make_float4((a.x - mean) * rstd * g0.x + e0.x,
                        (a.y - mean) * rstd * g0.y + e0.y,
                        (a.z - mean) * rstd * g0.z + e0.z,
                        (a.w - mean) * rstd * g0.w + e0.w);
    o4[t + 256] = make_float4((b.x - mean) * rstd * gA.x + eA.x,
                              (b.y - mean) * rstd * gA.y + eA.y,
                              (b.z - mean) * rstd * gA.z + eA.z,
                              (b.w - mean) * rstd * gA.w + eA.w);
}

// ---------------- host orchestration ---------------------------------------
static void run_gemm(int epi, const float* A, const float* B, const float* bias,
                     const float* extra, float* C, int M, int Nn, int Kk)
{
    dim3 grid(Nn / 128, M / 128), block(256);
    switch (epi) {
        case 0: gemm_tf32_kernel<0><<<grid, block>>>(A, B, bias, extra, C, M, Nn, Kk); break;
        case 1: gemm_tf32_kernel<1><<<grid, block>>>(A, B, bias, extra, C, M, Nn, Kk); break;
        case 2: gemm_tf32_kernel<2><<<grid, block>>>(A, B, bias, extra, C, M, Nn, Kk); break;
        case 3: gemm_tf32_kernel<3><<<grid, block>>>(A, B, bias, extra, C, M, Nn, Kk); break;
        case 4: gemm_tf32_kernel<4><<<grid, block>>>(A, B, bias, extra, C, M, Nn, Kk); break;
    }
}

extern "C" void kernel_launch(void* const* d_in, const int* in_sizes, int n_in,
                              void* d_out, int out_size)
{
    const float* E   = (const float*)d_in[0];
    const float* Obs = (const float*)d_in[1];
    const float* pw1 = (const float*)d_in[2];
    const float* pb1 = (const float*)d_in[3];
    const float* pw2 = (const float*)d_in[4];
    const float* pb2 = (const float*)d_in[5];
    const float* ow1 = (const float*)d_in[6];
    const float* ob1 = (const float*)d_in[7];
    const float* ow2 = (const float*)d_in[8];
    const float* ob2 = (const float*)d_in[9];
    const float* rw1 = (const float*)d_in[10];
    const float* rb1 = (const float*)d_in[11];
    const float* rw2 = (const float*)d_in[12];
    const float* rb2 = (const float*)d_in[13];
    const float* wq  = (const float*)d_in[14];
    const float* bq  = (const float*)d_in[15];
    const float* wk  = (const float*)d_in[16];
    const float* bk  = (const float*)d_in[17];
    const float* wv  = (const float*)d_in[18];
    const float* bv  = (const float*)d_in[19];
    const float* wo  = (const float*)d_in[20];
    const float* bo  = (const float*)d_in[21];
    const float* fw1 = (const float*)d_in[22];
    const float* fb1 = (const float*)d_in[23];
    const float* fw2 = (const float*)d_in[24];
    const float* fb2 = (const float*)d_in[25];
    const float* g1  = (const float*)d_in[26];
    const float* be1 = (const float*)d_in[27];
    const float* g2  = (const float*)d_in[28];
    const float* be2 = (const float*)d_in[29];
    float* out = (float*)d_out;

    float *t0, *t1, *P, *Dd, *R, *Q, *K, *V, *att, *X1, *F1;
    cudaGetSymbolAddress((void**)&t0,  g_t0);
    cudaGetSymbolAddress((void**)&t1,  g_t1);
    cudaGetSymbolAddress((void**)&P,   g_P);
    cudaGetSymbolAddress((void**)&Dd,  g_D);
    cudaGetSymbolAddress((void**)&R,   g_R);
    cudaGetSymbolAddress((void**)&Q,   g_Q);
    cudaGetSymbolAddress((void**)&K,   g_K);
    cudaGetSymbolAddress((void**)&V,   g_V);
    cudaGetSymbolAddress((void**)&att, g_att);
    cudaGetSymbolAddress((void**)&X1,  g_X1);
    cudaGetSymbolAddress((void**)&F1,  g_F1);

    // predictor MLP: P = relu(E@pw1+pb1) @ pw2 + pb2
    run_gemm(1, E,   pw1, pb1, nullptr, t0, NTOK, HID, HID);
    run_gemm(0, t0,  pw2, pb2, nullptr, P,  NTOK, HID, HID);
    // observation mapper, fused into D = P - (relu(Obs@ow1+ob1)@ow2+ob2)
    run_gemm(1, Obs, ow1, ob1, nullptr, t1, NTOK, HID, HID);
    run_gemm(3, t1,  ow2, ob2, P,       Dd, NTOK, HID, HID);
    // residual MLP: R = relu(D@rw1+rb1) @ rw2 + rb2
    run_gemm(1, Dd,  rw1, rb1, nullptr, t0, NTOK, HID, HID);
    run_gemm(0, t0,  rw2, rb2, nullptr, R,  NTOK, HID, HID);
    // Q/K/V projections
    run_gemm(0, E, wq, bq, nullptr, Q, NTOK, HID, HID);
    run_gemm(0, E, wk, bk, nullptr, K, NTOK, HID, HID);
    run_gemm(0, E, wv, bv, nullptr, V, NTOK, HID, HID);
    // per-token residual-adjusted attention
    attn_kernel<<<NTOK, 128>>>(Q, K, V, R, att);
    // output projection, fused residual add: t0 = E + att@wo + bo
    run_gemm(4, att, wo, bo, E, t0, NTOK, HID, HID);
    // X1 = LN(t0)
    ln_kernel<<<NTOK, 256>>>(t0, g1, be1, X1);
    // FFN: F1 = leaky(X1@fw1+fb1), t0 = X1 + F1@fw2 + fb2
    run_gemm(2, X1, fw1, fb1, nullptr, F1, NTOK, FFN, HID);
    run_gemm(4, F1, fw2, fb2, X1,      t0, NTOK, HID, FFN);
    // out = LN(t0)
    ln_kernel<<<NTOK, 256>>>(t0, g2, be2, out);
}

// round 4
// speedup vs baseline: 5.0021x; 4.9992x over previous
#include <cuda_runtime.h>
#include <cuda_pipeline.h>
#include <cuda_fp16.h>
#include <mma.h>
#include <math.h>
#include <stdint.h>

using namespace nvcuda;

#define NTOK 8192
#define HID 2048
#define FFN 8192
#define NHEAD 16
#define DHEAD 128
#define SZ_HH ((size_t)HID * HID)
#define SZ_NH ((size_t)NTOK * HID)
#define SZ_HF ((size_t)HID * FFN)
#define SZ_NF ((size_t)NTOK * FFN)

// ---------------- scratch (__device__ globals; no allocation) --------------
__device__ __half h_Epk[SZ_NH], h_Opk[SZ_NH], h_TP[SZ_NH], h_Dp[SZ_NH], h_F1[SZ_NF];
__device__ __half h_w0[SZ_HH], h_w1[SZ_HH], h_w2[SZ_HH], h_w3[SZ_HH], h_w4[SZ_HH];
__device__ __half h_w5[SZ_HH], h_w6[SZ_HH], h_w7[SZ_HH], h_w8[SZ_HH], h_w9[SZ_HH];
__device__ __half h_wf1[SZ_HF], h_wf2[SZ_HF];
__device__ float g_Rw[SZ_NH], g_Q[SZ_NH], g_K[SZ_NH], g_V[SZ_NH];

// ---------------- pack kernels ---------------------------------------------
// fp32 row-major -> fp16 row-major (4 elems/thread)
__global__ void pack_ah(const float* __restrict__ X, __half* __restrict__ out) {
    size_t u = ((size_t)blockIdx.x * 256 + threadIdx.x) * 4;
    float4 v = *(const float4*)(X + u);
    __half2 h0 = __floats2half2_rn(v.x, v.y);
    __half2 h1 = __floats2half2_rn(v.z, v.w);
    *(uint2*)(out + u) = make_uint2(*(uint32_t*)&h0, *(uint32_t*)&h1);
}
// W [Kd][Nd] fp32 -> out [Nd][Kd] fp16 (transpose)
__global__ void pack_bh(const float* __restrict__ W, __half* __restrict__ out, int Kd, int Nd) {
    __shared__ float s[32][65];
    const int k0 = blockIdx.x * 32, n0 = blockIdx.y * 64, t = threadIdx.x;
    #pragma unroll
    for (int i = 0; i < 8; i++) {
        int idx = t + i * 256, k = idx >> 6, n = idx & 63;
        s[k][n] = W[(size_t)(k0 + k) * Nd + n0 + n];
    }
    __syncthreads();
    #pragma unroll
    for (int i = 0; i < 2; i++) {
        int u = t + i * 256, n = u >> 3, kg = u & 7;
        __half2 h0 = __floats2half2_rn(s[kg * 4 + 0][n], s[kg * 4 + 1][n]);
        __half2 h1 = __floats2half2_rn(s[kg * 4 + 2][n], s[kg * 4 + 3][n]);
        *(uint2*)(out + (size_t)(n0 + n) * Kd + k0 + kg * 4) =
            make_uint2(*(uint32_t*)&h0, *(uint32_t*)&h1);
    }
}

// ---------------- fp16 wmma GEMM, 128x128 tile, BK=32, 3-stage cp.async ----
// A [M][Kd] fp16 row-major, Bm [Nd][Kd] fp16 (i.e. B^T), C = epi(A@B + bias)
// EPI: 0 bias, 1 relu, 2 leaky(0.01), 3 extra - x, 4 x + extra.  OPK: fp16 out.
#define BM 128
#define BN 128
#define BK 32
#define STG 3
#define ROWH 40
#define STAGE_H (BM * ROWH)
#define GEMM_SMEM (STG * STAGE_H * 2 * 2)

template<int EPI, bool OPK>
__global__ void __launch_bounds__(256, 2) gemm_h(
    const __half* __restrict__ A, const __half* __restrict__ Bm,
    const float* __restrict__ bias, const float* __restrict__ extra,
    void* __restrict__ Cv, int Nd, int Kd)
{
    extern __shared__ char smem[];
    __half* sA = (__half*)smem;
    __half* sB = sA + STG * STAGE_H;
    float*  sEp = (float*)smem;   // epilogue alias (after final sync)

    const int t = threadIdx.x, warp = t >> 5, lane = t & 31;
    const int bn = blockIdx.x, bm = blockIdx.y;
    const int wm = warp & 3, wn = warp >> 2;       // 4x2 warp grid, warp tile 32x64
    const int KT = Kd / BK;
    const __half* Ab = A + (size_t)bm * BM * Kd;
    const __half* Bb = Bm + (size_t)bn * BN * Kd;

    wmma::fragment<wmma::accumulator, 16, 16, 16, float> acc[2][4];
    #pragma unroll
    for (int i = 0; i < 2; i++)
        #pragma unroll
        for (int j = 0; j < 4; j++)
            wmma::fill_fragment(acc[i][j], 0.0f);

    auto load_tile = [&](int kt, int stg) {
        #pragma unroll
        for (int i = 0; i < 2; i++) {
            int c = t + i * 256, r = c >> 2, ch = c & 3;
            __pipeline_memcpy_async(sA + stg * STAGE_H + r * ROWH + ch * 8,
                                    Ab + (size_t)r * Kd + kt * BK + ch * 8, 16);
            __pipeline_memcpy_async(sB + stg * STAGE_H + r * ROWH + ch * 8,
                                    Bb + (size_t)r * Kd + kt * BK + ch * 8, 16);
        }
    };

    load_tile(0, 0); __pipeline_commit();
    load_tile(1, 1); __pipeline_commit();

    for (int kt = 0; kt < KT; ++kt) {
        __pipeline_wait_prior(1);
        __syncthreads();
        const int s = kt % STG;
        const __half* pA = sA + s * STAGE_H;
        const __half* pB = sB + s * STAGE_H;
        #pragma unroll
        for (int ks = 0; ks < 2; ++ks) {
            wmma::fragment<wmma::matrix_a, 16, 16, 16, __half, wmma::row_major> af[2];
            wmma::fragment<wmma::matrix_b, 16, 16, 16, __half, wmma::col_major> bf[4];
            #pragma unroll
            for (int fm = 0; fm < 2; ++fm)
                wmma::load_matrix_sync(af[fm], pA + (wm * 32 + fm * 16) * ROWH + ks * 16, ROWH);
            #pragma unroll
            for (int fn = 0; fn < 4; ++fn)
                wmma::load_matrix_sync(bf[fn], pB + (wn * 64 + fn * 16) * ROWH + ks * 16, ROWH);
            #pragma unroll
            for (int fm = 0; fm < 2; ++fm)
                #pragma unroll
                for (int fn = 0; fn < 4; ++fn)
                    wmma::mma_sync(acc[fm][fn], af[fm], bf[fn], acc[fm][fn]);
        }
        if (kt + 2 < KT) load_tile(kt + 2, (kt + 2) % STG);
        __pipeline_commit();
    }
    __syncthreads();

    // epilogue via per-warp smem scratch
    const size_t row0 = (size_t)bm * BM;
    const int    col0 = bn * BN;
    #pragma unroll
    for (int fm = 0; fm < 2; ++fm) {
        #pragma unroll
        for (int fn = 0; fn < 4; ++fn) {
            wmma::store_matrix_sync(&sEp[warp * 256], acc[fm][fn], 16, wmma::mem_row_major);
            __syncwarp();
            const int r0 = wm * 32 + fm * 16;
            const int c0 = wn * 64 + fn * 16;
            #pragma unroll
            for (int e = lane; e < 256; e += 32) {
                int r = e >> 4, c = e & 15;
                size_t gr = row0 + r0 + r;
                int    gc = col0 + c0 + c;
                float  v  = sEp[warp * 256 + e] + bias[gc];
                if (EPI == 1) v = fmaxf(v, 0.0f);
                else if (EPI == 2) v = (v >= 0.0f) ? v : 0.01f * v;
                else if (EPI == 3) v = extra[gr * (size_t)Nd + gc] - v;
                else if (EPI == 4) v = v + extra[gr * (size_t)Nd + gc];
                if (OPK) ((__half*)Cv)[gr * (size_t)Nd + gc] = __float2half_rn(v);
                else     ((float*)Cv)[gr * (size_t)Nd + gc] = v;
            }
            __syncwarp();
        }
    }
}

// ---------------- per-token head-vs-head attention (exact fp32) ------------
__global__ void __launch_bounds__(128) attn_kernel(
    const float* __restrict__ Q, const float* __restrict__ K,
    const float* __restrict__ V, const float* __restrict__ R,
    __half* __restrict__ outp)
{
    __shared__ __align__(16) float sQ[NHEAD][DHEAD], sK[NHEAD][DHEAD],
                                   sV[NHEAD][DHEAD], sR[NHEAD][DHEAD];
    const int n = blockIdx.x, t = threadIdx.x;
    const size_t base = (size_t)n * HID;
    #pragma unroll
    for (int i = t; i < HID / 4; i += 128) {
        ((float4*)sQ)[i] = ((const float4*)(Q + base))[i];
        ((float4*)sK)[i] = ((const float4*)(K + base))[i];
        ((float4*)sV)[i] = ((const float4*)(V + base))[i];
        ((float4*)sR)[i] = ((const float4*)(R + base))[i];
    }
    __syncthreads();
    const int warp = t >> 5, lane = t & 31;
    const float scale = 0.08838834764831845f;
    #pragma unroll
    for (int hh = 0; hh < 4; ++hh) {
        const int h = warp * 4 + hh;
        const float q0 = sQ[h][lane], q1 = sQ[h][lane + 32],
                    q2 = sQ[h][lane + 64], q3 = sQ[h][lane + 96];
        float sc[NHEAD];
        #pragma unroll
        for (int g = 0; g < NHEAD; ++g) {
            float s1 = q0 * sK[g][lane] + q1 * sK[g][lane + 32]
                     + q2 * sK[g][lane + 64] + q3 * sK[g][lane + 96];
            float s2 = q0 * sR[g][lane] + q1 * sR[g][lane + 32]
                     + q2 * sR[g][lane + 64] + q3 * sR[g][lane + 96];
            float v = s1 * scale - s2;
            #pragma unroll
            for (int o = 16; o > 0; o >>= 1) v += __shfl_xor_sync(0xffffffffu, v, o);
            sc[g] = v;
        }
        float m = sc[0];
        #pragma unroll
        for (int g = 1; g < NHEAD; ++g) m = fmaxf(m, sc[g]);
        float den = 0.f;
        #pragma unroll
        for (int g = 0; g < NHEAD; ++g) { sc[g] = expf(sc[g] - m); den += sc[g]; }
        const float inv = 1.0f / den;
        float o0 = 0, o1 = 0, o2 = 0, o3 = 0;
        #pragma unroll
        for (int g = 0; g < NHEAD; ++g) {
            float p = sc[g] * inv;
            o0 += p * sV[g][lane];      o1 += p * sV[g][lane + 32];
            o2 += p * sV[g][lane + 64]; o3 += p * sV[g][lane + 96];
        }
        __half* op = outp + base + (size_t)h * DHEAD;
        op[lane]      = __float2half_rn(o0);
        op[lane + 32] = __float2half_rn(o1);
        op[lane + 64] = __float2half_rn(o2);
        op[lane + 96] = __float2half_rn(o3);
    }
}

// ---------------- layernorm; optional fp16 copy ----------------------------
template<bool PK2>
__global__ void __launch_bounds__(256) ln_kernel(
    const float* __restrict__ x, const float* __restrict__ gamma,
    const float* __restrict__ beta, float* __restrict__ outr,
    __half* __restrict__ outp)
{
    __shared__ float sh[8];
    const int row = blockIdx.x, t = threadIdx.x, lane = t & 31, w = t >> 5;
    const float4* xr = (const float4*)(x + (size_t)row * HID);
    float4 a = xr[t], b = xr[t + 256];
    float s = a.x + a.y + a.z + a.w + b.x + b.y + b.z + b.w;
    #pragma unroll
    for (int o = 16; o > 0; o >>= 1) s += __shfl_xor_sync(0xffffffffu, s, o);
    if (lane == 0) sh[w] = s;
    __syncthreads();
    float tot = 0;
    #pragma unroll
    for (int i = 0; i < 8; i++) tot += sh[i];
    const float mean = tot * (1.0f / HID);
    float d, sq = 0;
    d = a.x - mean; sq += d * d; d = a.y - mean; sq += d * d;
    d = a.z - mean; sq += d * d; d = a.w - mean; sq += d * d;
    d = b.x - mean; sq += d * d; d = b.y - mean; sq += d * d;
    d = b.z - mean; sq += d * d; d = b.w - mean; sq += d * d;
    __syncthreads();
    #pragma unroll
    for (int o = 16; o > 0; o >>= 1) sq += __shfl_xor_sync(0xffffffffu, sq, o);
    if (lane == 0) sh[w] = sq;
    __syncthreads();
    tot = 0;
    #pragma unroll
    for (int i = 0; i < 8; i++) tot += sh[i];
    const float rstd = rsqrtf(tot * (1.0f / HID) + 1e-5f);
    float4 g0 = ((const float4*)gamma)[t], gA = ((const float4*)gamma)[t + 256];
    float4 e0 = ((const float4*)beta)[t],  eA = ((const float4*)beta)[t + 256];
    float4 r0 = make_float4((a.x - mean) * rstd * g0.x + e0.x, (a.y - mean) * rstd * g0.y + e0.y,
                            (a.z - mean) * rstd * g0.z + e0.z, (a.w - mean) * rstd * g0.w + e0.w);
    float4 r1 = make_float4((b.x - mean) * rstd * gA.x + eA.x, (b.y - mean) * rstd * gA.y + eA.y,
                            (b.z - mean) * rstd * gA.z + eA.z, (b.w - mean) * rstd * gA.w + eA.w);
    float4* o4 = (float4*)(outr + (size_t)row * HID);
    o4[t] = r0; o4[t + 256] = r1;
    if (PK2) {
        __half2 p0 = __floats2half2_rn(r0.x, r0.y), p1 = __floats2half2_rn(r0.z, r0.w);
        __half2 p2 = __floats2half2_rn(r1.x, r1.y), p3 = __floats2half2_rn(r1.z, r1.w);
        __half* op = outp + (size_t)row * HID;
        *(uint2*)(op + t * 4)        = make_uint2(*(uint32_t*)&p0, *(uint32_t*)&p1);
        *(uint2*)(op + t * 4 + 1024) = make_uint2(*(uint32_t*)&p2, *(uint32_t*)&p3);
    }
}

// ---------------- host ------------------------------------------------------
template<int EPI, bool OPK>
static void G(const __half* A, const __half* B, const float* bias, const float* extra,
              void* C, int Nd, int Kd)
{
    cudaFuncSetAttribute(gemm_h<EPI, OPK>, cudaFuncAttributeMaxDynamicSharedMemorySize, GEMM_SMEM);
    gemm_h<EPI, OPK><<<dim3(Nd / BN, NTOK / BM), 256, GEMM_SMEM>>>(A, B, bias, extra, C, Nd, Kd);
}

extern "C" void kernel_launch(void* const* d_in, const int* in_sizes, int n_in,
                              void* d_out, int out_size)
{
    const float* in[30];
    for (int i = 0; i < 30; i++) in[i] = (const float*)d_in[i];
    const float *E = in[0], *Obs = in[1];
    float* out = (float*)d_out;

    __half *Epk, *Opk, *TP, *Dp, *F1, *W[12];
    float *Rw, *Q, *K, *V;
    cudaGetSymbolAddress((void**)&Epk, h_Epk); cudaGetSymbolAddress((void**)&Opk, h_Opk);
    cudaGetSymbolAddress((void**)&TP,  h_TP);  cudaGetSymbolAddress((void**)&Dp,  h_Dp);
    cudaGetSymbolAddress((void**)&F1,  h_F1);
    cudaGetSymbolAddress((void**)&W[0], h_w0); cudaGetSymbolAddress((void**)&W[1], h_w1);
    cudaGetSymbolAddress((void**)&W[2], h_w2); cudaGetSymbolAddress((void**)&W[3], h_w3);
    cudaGetSymbolAddress((void**)&W[4], h_w4); cudaGetSymbolAddress((void**)&W[5], h_w5);
    cudaGetSymbolAddress((void**)&W[6], h_w6); cudaGetSymbolAddress((void**)&W[7], h_w7);
    cudaGetSymbolAddress((void**)&W[8], h_w8); cudaGetSymbolAddress((void**)&W[9], h_w9);
    cudaGetSymbolAddress((void**)&W[10], h_wf1); cudaGetSymbolAddress((void**)&W[11], h_wf2);
    cudaGetSymbolAddress((void**)&Rw, g_Rw); cudaGetSymbolAddress((void**)&Q, g_Q);
    cudaGetSymbolAddress((void**)&K,  g_K);  cudaGetSymbolAddress((void**)&V, g_V);

    // pack weights (transpose to [N][K] fp16) + inputs (fp16 row-major)
    dim3 hh(HID / 32, HID / 64);
    for (int i = 0; i < 10; i++)
        pack_bh<<<hh, 256>>>(in[2 + 2 * i], W[i], HID, HID);
    pack_bh<<<dim3(HID / 32, FFN / 64), 256>>>(in[22], W[10], HID, FFN);
    pack_bh<<<dim3(FFN / 32, HID / 64), 256>>>(in[24], W[11], FFN, HID);
    pack_ah<<<SZ_NH / 1024, 256>>>(E,   Epk);
    pack_ah<<<SZ_NH / 1024, 256>>>(Obs, Opk);

    // predictor MLP: P
    G<1, true >(Epk, W[0], in[3],  nullptr, TP, HID, HID);    // t0 = relu(E@pw1)
    G<0, false>(TP,  W[1], in[5],  nullptr, Rw, HID, HID);    // P (fp32)
    // observation MLP fused: D = P - (relu(Obs@ow1)@ow2 + ob2)
    G<1, true >(Opk, W[2], in[7],  nullptr, TP, HID, HID);    // t1
    G<3, true >(TP,  W[3], in[9],  Rw,      Dp, HID, HID);    // D (fp16)
    // residual MLP: R
    G<1, true >(Dp,  W[4], in[11], nullptr, TP, HID, HID);    // t2
    G<0, false>(TP,  W[5], in[13], nullptr, Rw, HID, HID);    // R (fp32)
    // QKV (fp32, exact attention inputs)
    G<0, false>(Epk, W[6], in[15], nullptr, Q, HID, HID);
    G<0, false>(Epk, W[7], in[17], nullptr, K, HID, HID);
    G<0, false>(Epk, W[8], in[19], nullptr, V, HID, HID);
    attn_kernel<<<NTOK, 128>>>(Q, K, V, Rw, TP);              // att (fp16)
    G<4, false>(TP, W[9], in[21], E, Rw, HID, HID);           // t3 = E + att@wo (fp32)
    ln_kernel<true><<<NTOK, 256>>>(Rw, in[26], in[27], Q, TP); // X1 fp32 in Q, fp16 in TP
    G<2, true >(TP, W[10], in[23], nullptr, F1, FFN, HID);    // F1 = leaky(X1@fw1) (fp16)
    G<4, false>(F1, W[11], in[25], Q, Rw, HID, FFN);          // t4 = X1 + F1@fw2 (fp32)
    ln_kernel<false><<<NTOK, 256>>>(Rw, in[28], in[29], out, nullptr);
}